// round 7
// baseline (speedup 1.0000x reference)
#include <cuda_runtime.h>
#include <cuda_bf16.h>

#define BB 4
#define MM 2048
#define HH 16
#define NJ 12
#define SCALE 0.3535533905932738f   // (128//16)^-0.5

__constant__ float c_F[NJ] = {
    1.0f, 1.0f, 5.0e-1f, 1.6666666666666666e-1f,
    4.1666666666666664e-2f, 8.3333333333333332e-3f,
    1.3888888888888889e-3f, 1.9841269841269841e-4f,
    2.4801587301587302e-5f, 2.7557319223985893e-6f,
    2.7557319223985894e-7f, 2.5052108385441720e-8f
};

// Dynamic smem layout (floats):
//   qf   [0, 4096)            : (wq,wf) interleaved, [s*256 + 2d + {0,1}]
//   kvw  [4096, 8448)         : (wk,wv) interleaved, row d2 (68 floats), col 4t
//   grp  [8448 + g*3648)      : Kpow [0,1536) = [j*128+p]
//                               ivq  [1536,3648) = Qpow [j*132+p] then iv [t*132+p]
#define SM_KV   4096
#define SM_GRP  8448
#define GRP_SZ  3648
#define GRP_IVQ 1536
#define SM_TOT  37632   // 8448 + 8*3648 = 37632 floats = 150528 bytes

__global__ void __launch_bounds__(1024, 1)
k_all(const float* __restrict__ query, const float* __restrict__ key_,
      const float* __restrict__ value, const float* __restrict__ wq,
      const float* __restrict__ wk,    const float* __restrict__ wv,
      const float* __restrict__ wf,    const float* __restrict__ lnw,
      const float* __restrict__ lnb,   float* __restrict__ out) {
    extern __shared__ float dsm[];
    const int b    = blockIdx.x;
    const int tid  = threadIdx.x;
    const int g    = tid >> 7;      // group (8 groups of 128 threads)
    const int p    = tid & 127;     // position within head
    const int lane = tid & 31;
    const int warp = tid >> 5;

    __shared__ float Ash[256];          // A(s,t) at [s*16+t]
    __shared__ float Gsh[256];          // G(t,s) at [t*16+s]
    __shared__ float SA[NJ * 16];       // [j*16+t]
    __shared__ float AG[NJ * 16];       // [j*16+t]
    __shared__ float QMs[8][16];        // [g][j]
    __shared__ float czU[8][16][16];    // phase A: cz[g][t][j]; phase B: U[g][j][t]
    __shared__ float Wf[8][16];         // [g][j]
    __shared__ float redS[32], redS2[32];
    __shared__ float mu_s, rs_s;

    float* qf  = dsm;
    float* kvw = dsm + SM_KV;
    float* Kp  = dsm + SM_GRP + g * GRP_SZ;
    float* ivq = Kp + GRP_IVQ;

    // ---- prefetch all global inputs into registers (hide DRAM/L2 latency) ----
    const int gi0 = b * MM + tid;       // head g,   pos p  (m = tid)
    const float qv0 = query[gi0], kv0 = key_[gi0], vv0 = value[gi0];
    const float qv1 = query[gi0 + 1024], kv1 = key_[gi0 + 1024], vv1 = value[gi0 + 1024];
    const float lw0 = lnw[tid], lb0 = lnb[tid];
    const float lw1 = lnw[tid + 1024], lb1 = lnb[tid + 1024];

    // ---- stage weights: interleaved float4 layouts (2 f4 loads / thread) ----
    if (tid < 512) {
        float4 a = ((const float4*)wq)[tid];
        float4 f = ((const float4*)wf)[tid];
        int st = tid >> 5, off = tid & 31;
        float* q0 = qf + st * 256 + 8 * off;
        ((float4*)q0)[0] = make_float4(a.x, f.x, a.y, f.y);
        ((float4*)q0)[1] = make_float4(a.z, f.z, a.w, f.w);
    } else {
        int i4 = tid - 512;
        float4 kk = ((const float4*)wk)[i4];
        float4 vv = ((const float4*)wv)[i4];
        int st = i4 >> 5, off = i4 & 31;
        *(float4*)(kvw + (off * 2) * 68 + 4 * st)     = make_float4(kk.x, vv.x, kk.y, vv.y);
        *(float4*)(kvw + (off * 2 + 1) * 68 + 4 * st) = make_float4(kk.z, vv.z, kk.w, vv.w);
    }
    __syncthreads();

    // ---- A(s,t), G(t,s): 256 dual dots, 4 threads per pair (16 f4 iters each) ----
    {
        int pair = tid >> 2, c = tid & 3;
        int s = pair >> 4, t = pair & 15;
        const float4* qp = (const float4*)(qf + s * 256);
        const float4* kp = (const float4*)(kvw + 4 * t);
        float a = 0.f, gv = 0.f;
#pragma unroll
        for (int i = 0; i < 16; i++) {
            int d2 = c + 4 * i;         // interleaved chunks (bank-friendly)
            float4 q = qp[d2];
            float4 x = kp[d2 * 17];
            a  = fmaf(q.x, x.x, a);  gv = fmaf(q.y, x.y, gv);
            a  = fmaf(q.z, x.z, a);  gv = fmaf(q.w, x.w, gv);
        }
        a  += __shfl_xor_sync(0xffffffffu, a, 1);  a  += __shfl_xor_sync(0xffffffffu, a, 2);
        gv += __shfl_xor_sync(0xffffffffu, gv, 1); gv += __shfl_xor_sync(0xffffffffu, gv, 2);
        if (c == 0) { Ash[s * 16 + t] = SCALE * a; Gsh[t * 16 + s] = gv; }
    }
    __syncthreads();

    // ---- SA/AG series (warps 0-1) || pass-0 powers (all threads) ----
    if (tid < 64) {
        int tt = tid >> 2, qq = tid & 3;
        float4 g4 = *(const float4*)(Gsh + tt * 16 + qq * 4);
        float a0 = Ash[(qq * 4 + 0) * 16 + tt];
        float a1 = Ash[(qq * 4 + 1) * 16 + tt];
        float a2 = Ash[(qq * 4 + 2) * 16 + tt];
        float a3 = Ash[(qq * 4 + 3) * 16 + tt];
        float p0 = 1.f, p1 = 1.f, p2 = 1.f, p3 = 1.f;
#pragma unroll
        for (int j = 0; j < NJ; j++) {
            float sa = (p0 + p1) + (p2 + p3);
            float ag = fmaf(p0, g4.x, fmaf(p1, g4.y, fmaf(p2, g4.z, p3 * g4.w)));
            sa += __shfl_xor_sync(0xffffffffu, sa, 1);
            sa += __shfl_xor_sync(0xffffffffu, sa, 2);
            ag += __shfl_xor_sync(0xffffffffu, ag, 1);
            ag += __shfl_xor_sync(0xffffffffu, ag, 2);
            if (qq == 0) { SA[j * 16 + tt] = sa; AG[j * 16 + tt] = ag; }
            p0 *= a0; p1 *= a1; p2 *= a2; p3 *= a3;
        }
    }
    {   // pass-0 K/Q powers
        float kp = 1.f, qp = 1.f;
#pragma unroll
        for (int j = 0; j < NJ; j++) {
            Kp[j * 128 + p]  = kp;
            ivq[j * 132 + p] = qp;
            kp *= kv0; qp *= qv0;
        }
    }
    __syncthreads();

    float yreg[2];

#pragma unroll
    for (int pass = 0; pass < 2; pass++) {
        const float kval = pass ? kv1 : kv0;
        const float qval = pass ? qv1 : qv0;
        const float vval = pass ? vv1 : vv0;

        if (pass) {   // pass-1 powers (pass-0 written above)
            float kp = 1.f, qp = 1.f;
#pragma unroll
            for (int j = 0; j < NJ; j++) {
                Kp[j * 128 + p]  = kp;
                ivq[j * 132 + p] = qp;
                kp *= kval; qp *= qval;
            }
            __syncthreads();
        }

        // ---- QM_j per head: warp w -> head (w>>2), 3 j's each ----
        {
            int gw = warp >> 2, j0 = 3 * (warp & 3);
            const float* qpow = dsm + SM_GRP + gw * GRP_SZ + GRP_IVQ;
#pragma unroll
            for (int jj = 0; jj < 3; jj++) {
                int j = j0 + jj;
                float4 x = *(const float4*)(qpow + j * 132 + lane * 4);
                float s = (x.x + x.y) + (x.z + x.w);
#pragma unroll
                for (int o = 16; o; o >>= 1) s += __shfl_down_sync(0xffffffffu, s, o);
                if (lane == 0) QMs[gw][j] = s;
            }
        }
        __syncthreads();

        // ---- cz[g][t][j] = F_j * QM_j * SA_j(t) : 1536 entries ----
#pragma unroll
        for (int rep = 0; rep < 2; rep++) {
            int i = tid + rep * 1024;
            if (i < 1536) {
                int gg = i / 192; int r = i - gg * 192;
                int jj = r >> 4, t = r & 15;
                czU[gg][t][jj] = c_F[jj] * QMs[gg][jj] * SA[jj * 16 + t];
            }
        }
        __syncthreads();

        // ---- Z(p,t) Horner in K_p; iv[t][p] = V_p / Z (overwrites Qpow) ----
        {
            const float4* c4 = (const float4*)&czU[g][0][0];
#pragma unroll
            for (int t = 0; t < 16; t++) {
                float4 c0 = c4[t * 4 + 0];
                float4 c1 = c4[t * 4 + 1];
                float4 c2 = c4[t * 4 + 2];
                float z = c2.w;
                z = fmaf(z, kval, c2.z); z = fmaf(z, kval, c2.y); z = fmaf(z, kval, c2.x);
                z = fmaf(z, kval, c1.w); z = fmaf(z, kval, c1.z); z = fmaf(z, kval, c1.y);
                z = fmaf(z, kval, c1.x);
                z = fmaf(z, kval, c0.w); z = fmaf(z, kval, c0.z); z = fmaf(z, kval, c0.y);
                z = fmaf(z, kval, c0.x);
                ivq[t * 132 + p] = __fdividef(vval, z);
            }
        }
        __syncthreads();

        // ---- U[g][j][t] = sum_p Kpow[j][p] * iv[t][p]  (into czU) ----
#pragma unroll
        for (int rep = 0; rep < 2; rep++) {
            int i = tid + rep * 1024;
            if (i < 1536) {
                int gg = i / 192; int r = i - gg * 192;
                int jj = r >> 4, t = r & 15;
                const float* base = dsm + SM_GRP + gg * GRP_SZ;
                const float4* kp4 = (const float4*)(base + jj * 128);
                const float4* iv4 = (const float4*)(base + GRP_IVQ + t * 132);
                float u = 0.f;
#pragma unroll
                for (int q = 0; q < 32; q++) {
                    float4 a = kp4[q], x = iv4[q];
                    u = fmaf(a.x, x.x, u); u = fmaf(a.y, x.y, u);
                    u = fmaf(a.z, x.z, u); u = fmaf(a.w, x.w, u);
                }
                czU[gg][jj][t] = u;
            }
        }
        __syncthreads();

        // ---- Wf[g][j] = F_j * sum_t AG[j][t] * U[j][t] ----
        if (tid < 96) {
            int gg = tid / 12, jj = tid - gg * 12;
            const float4* u4 = (const float4*)&czU[gg][jj][0];
            const float4* a4 = (const float4*)(AG + jj * 16);
            float s = 0.f;
#pragma unroll
            for (int q = 0; q < 4; q++) {
                float4 u = u4[q], a = a4[q];
                s = fmaf(u.x, a.x, s); s = fmaf(u.y, a.y, s);
                s = fmaf(u.z, a.z, s); s = fmaf(u.w, a.w, s);
            }
            Wf[gg][jj] = c_F[jj] * s;
        }
        __syncthreads();

        // ---- y = q + sum_j Wf[j] q^j (stays in registers!) ----
        {
            float val = Wf[g][NJ - 1];
#pragma unroll
            for (int j = NJ - 2; j >= 0; j--) val = fmaf(val, qval, Wf[g][j]);
            yreg[pass] = qval + val;
        }
    }
    __syncthreads();   // Wf reads done before anything else (paranoia; also orders LN)

    // ---- in-block LayerNorm over all 2048 y values (2 per thread) ----
    float s1 = yreg[0] + yreg[1];
    float s2 = yreg[0] * yreg[0] + yreg[1] * yreg[1];
#pragma unroll
    for (int o = 16; o; o >>= 1) {
        s1 += __shfl_down_sync(0xffffffffu, s1, o);
        s2 += __shfl_down_sync(0xffffffffu, s2, o);
    }
    if (lane == 0) { redS[warp] = s1; redS2[warp] = s2; }
    __syncthreads();
    if (warp == 0) {
        float a = redS[lane], c = redS2[lane];
#pragma unroll
        for (int o = 16; o; o >>= 1) {
            a += __shfl_down_sync(0xffffffffu, a, o);
            c += __shfl_down_sync(0xffffffffu, c, o);
        }
        if (lane == 0) {
            float mu  = a * (1.0f / MM);
            float var = c * (1.0f / MM) - mu * mu;
            mu_s = mu;
            rs_s = rsqrtf(var + 1e-5f);
        }
    }
    __syncthreads();
    const float mu = mu_s, rs = rs_s;
    out[b * MM + tid]        = (yreg[0] - mu) * rs * lw0 + lb0;
    out[b * MM + tid + 1024] = (yreg[1] - mu) * rs * lw1 + lb1;
}

extern "C" void kernel_launch(void* const* d_in, const int* in_sizes, int n_in,
                              void* d_out, int out_size) {
    const float* query = (const float*)d_in[0];
    const float* key_  = (const float*)d_in[1];
    const float* value = (const float*)d_in[2];
    const float* wq    = (const float*)d_in[3];
    const float* wk    = (const float*)d_in[4];
    const float* wv    = (const float*)d_in[5];
    const float* wf    = (const float*)d_in[6];
    const float* lw    = (const float*)d_in[7];
    const float* lb    = (const float*)d_in[8];
    float* out = (float*)d_out;

    const size_t dyn = SM_TOT * sizeof(float);   // 150528 B
    cudaFuncSetAttribute(k_all, cudaFuncAttributeMaxDynamicSharedMemorySize, (int)dyn);
    k_all<<<BB, 1024, dyn>>>(query, key_, value, wq, wk, wv, wf, lw, lb, out);
}

// round 8
// speedup vs baseline: 2.1059x; 2.1059x over previous
#include <cuda_runtime.h>
#include <cuda_bf16.h>

#define BB 4
#define MM 2048
#define HH 16
#define NJ 12
#define SCALE 0.3535533905932738f   // (128//16)^-0.5

__constant__ float c_F[NJ] = {
    1.0f, 1.0f, 5.0e-1f, 1.6666666666666666e-1f,
    4.1666666666666664e-2f, 8.3333333333333332e-3f,
    1.3888888888888889e-3f, 1.9841269841269841e-4f,
    2.4801587301587302e-5f, 2.7557319223985893e-6f,
    2.7557319223985894e-7f, 2.5052108385441720e-8f
};

__device__ float g_y[BB * MM];   // residual + attention output (pre-LN)
__device__ int   g_cnt[BB];      // zero-init; self-resetting every run

// Overlay layout (floats), region size 8448:
//   phase S (staging):  qf [0,4096) = (wq,wf) interleaved [s*256+2d+{0,1}]
//                       kvw[4096,8448) = (wk,wv) interleaved [d2*68+4t+{0..3}]
//   phase P (post-dot): Kpow [0,1536)      = [j*128+p]
//                       Qpow [1536,3120)   = [j*132+p]
//                       Apow [3120,6192)   = [j*256+s*16+t]
//                       iv   [3120,5232)   = [t*132+p]  (overwrites Apow later)

__global__ void __launch_bounds__(512, 1)
k_fused(const float* __restrict__ query, const float* __restrict__ key_,
        const float* __restrict__ value, const float* __restrict__ wq,
        const float* __restrict__ wk,    const float* __restrict__ wv,
        const float* __restrict__ wf,    const float* __restrict__ lnw,
        const float* __restrict__ lnb,   float* __restrict__ out) {
    const int b    = blockIdx.x >> 4;
    const int h    = blockIdx.x & 15;
    const int tid  = threadIdx.x;
    const int lane = tid & 31;
    const int warp = tid >> 5;

    __shared__ float ovl[8448];
    __shared__ float Ash[256];      // A(s,t) at [s*16+t]
    __shared__ float Gts[256];      // G(t,s) at [s*16+t]  (s-major!)
    __shared__ float Qs[128], Ks[128], Vs[128];
    __shared__ float SA[NJ * 16];   // [j*16+t]
    __shared__ float AG[NJ * 16];   // [j*16+t]
    __shared__ float cz[256];       // [t*16+j], j<12 used
    __shared__ float QMs[16];
    __shared__ float U[NJ * 16];    // [j*16+t]
    __shared__ float Wf[NJ];
    __shared__ float redS[16], redS2[16];
    __shared__ float mu_s, rs_s;
    __shared__ int   isLast;

    float* Kpow = ovl;
    float* Qpow = ovl + 1536;
    float* Apow = ovl + 3120;
    float* iv   = ovl + 3120;

    // ---- register prefetch: per-head q/k/v + LN params (for possible tail) ----
    float qv = 0.f, kval = 0.f, vval = 0.f;
    if (tid < 128) {
        int gi = b * MM + h * 128 + tid;
        qv = query[gi]; kval = key_[gi]; vval = value[gi];
    }
    const float4 lw4 = ((const float4*)lnw)[tid];
    const float4 lb4 = ((const float4*)lnb)[tid];

    // ---- stage weights: 4 f4 LDG + 4 f4 STS per thread ----
    {
        float4 a  = ((const float4*)wq)[tid];
        float4 f  = ((const float4*)wf)[tid];
        float4 kk = ((const float4*)wk)[tid];
        float4 vw = ((const float4*)wv)[tid];
        int st = tid >> 5, off = tid & 31;
        float* q0 = ovl + st * 256 + 8 * off;
        ((float4*)q0)[0] = make_float4(a.x, f.x, a.y, f.y);
        ((float4*)q0)[1] = make_float4(a.z, f.z, a.w, f.w);
        float* kb = ovl + 4096;
        *(float4*)(kb + (off * 2) * 68 + 4 * st)     = make_float4(kk.x, vw.x, kk.y, vw.y);
        *(float4*)(kb + (off * 2 + 1) * 68 + 4 * st) = make_float4(kk.z, vw.z, kk.w, vw.w);
    }
    if (tid < 128) { Qs[tid] = qv; Ks[tid] = kval; Vs[tid] = vval; }
    __syncthreads();

    // ---- A(s,t), G(t,s): 256 dual dots, 2 threads per pair ----
    {
        int pair = tid >> 1, c = tid & 1;
        int s = pair >> 4, t = pair & 15;
        const float4* qp = (const float4*)(ovl + s * 256);
        const float4* kp = (const float4*)(ovl + 4096 + 4 * t);
        float a = 0.f, g = 0.f;
#pragma unroll
        for (int i = 0; i < 32; i++) {
            int d2 = c + 2 * i;
            float4 q = qp[d2];
            float4 x = kp[d2 * 17];
            a = fmaf(q.x, x.x, a);  g = fmaf(q.y, x.y, g);
            a = fmaf(q.z, x.z, a);  g = fmaf(q.w, x.w, g);
        }
        a += __shfl_xor_sync(0xffffffffu, a, 1);
        g += __shfl_xor_sync(0xffffffffu, g, 1);
        if (c == 0) { Ash[s * 16 + t] = SCALE * a; Gts[s * 16 + t] = g; }
    }
    __syncthreads();   // staging dead -> overlay

    // ---- P1: K/Q powers (tid<128) || Apow table (tid 128..383) ----
    if (tid < 128) {
        float kp = 1.f, qp = 1.f;
#pragma unroll
        for (int j = 0; j < NJ; j++) {
            Kpow[j * 128 + tid] = kp;
            Qpow[j * 132 + tid] = qp;
            kp *= kval; qp *= qv;
        }
    } else if (tid < 384) {
        int idx = tid - 128;                 // idx = s*16 + t
        float a = Ash[idx];
        float pw = 1.f;
#pragma unroll
        for (int j = 0; j < NJ; j++) {
            Apow[j * 256 + idx] = pw;
            pw *= a;
        }
    }
    __syncthreads();

    // ---- P2: SA/AG reductions (tid<192) || QM_j (tid 192..287) ----
    if (tid < 192) {
        int j = tid >> 4, t = tid & 15;
        float sa = 0.f, ag = 0.f;
        const float* ap = Apow + j * 256 + t;
        const float* gp = Gts + t;
#pragma unroll
        for (int s = 0; s < 16; s++) {
            float pw = ap[s * 16];
            sa += pw;
            ag = fmaf(pw, gp[s * 16], ag);
        }
        SA[j * 16 + t] = sa;
        AG[j * 16 + t] = ag;
    } else if (tid < 288) {
        int idx = tid - 192;
        int j = idx >> 3, oct = idx & 7;     // 8 threads per j
        const float4* qp4 = (const float4*)(Qpow + j * 132) + oct * 4;
        float4 x0 = qp4[0], x1 = qp4[1], x2 = qp4[2], x3 = qp4[3];
        float s = ((x0.x + x0.y) + (x0.z + x0.w)) + ((x1.x + x1.y) + (x1.z + x1.w))
                + ((x2.x + x2.y) + (x2.z + x2.w)) + ((x3.x + x3.y) + (x3.z + x3.w));
        s += __shfl_xor_sync(0xffffffffu, s, 1);
        s += __shfl_xor_sync(0xffffffffu, s, 2);
        s += __shfl_xor_sync(0xffffffffu, s, 4);
        if (oct == 0) QMs[j] = s;
    }
    __syncthreads();

    // ---- P3: cz[t][j] = F_j * QM_j * SA_j(t) ----
    if (tid < 192) {
        int j = tid >> 4, t = tid & 15;
        cz[t * 16 + j] = c_F[j] * QMs[j] * SA[j * 16 + t];
    }
    __syncthreads();

    // ---- P4: Z(p,t) Horner; iv[t][p] = V_p / Z   (512 threads, 4 t's each) ----
    {
        int p = tid & 127, tq = tid >> 7;
        float k = Ks[p], v = Vs[p];
        const float4* c4 = (const float4*)cz;
#pragma unroll
        for (int tt = 0; tt < 4; tt++) {
            int t = tq * 4 + tt;
            float4 c0 = c4[t * 4 + 0];
            float4 c1 = c4[t * 4 + 1];
            float4 c2 = c4[t * 4 + 2];
            float z = c2.w;
            z = fmaf(z, k, c2.z); z = fmaf(z, k, c2.y); z = fmaf(z, k, c2.x);
            z = fmaf(z, k, c1.w); z = fmaf(z, k, c1.z); z = fmaf(z, k, c1.y);
            z = fmaf(z, k, c1.x);
            z = fmaf(z, k, c0.w); z = fmaf(z, k, c0.z); z = fmaf(z, k, c0.y);
            z = fmaf(z, k, c0.x);
            iv[t * 132 + p] = __fdividef(v, z);
        }
    }
    __syncthreads();

    // ---- P5: U[j][t] = sum_p Kpow[j][p]*iv[t][p]  (2 threads per element) ----
    if (tid < 384) {
        int jt = tid >> 1, c = tid & 1;
        int j = jt >> 4, t = jt & 15;
        const float4* kp4 = (const float4*)(Kpow + j * 128) + c * 16;
        const float4* iv4 = (const float4*)(iv + t * 132) + c * 16;
        float u = 0.f;
#pragma unroll
        for (int q = 0; q < 16; q++) {
            float4 a = kp4[q], x = iv4[q];
            u = fmaf(a.x, x.x, u); u = fmaf(a.y, x.y, u);
            u = fmaf(a.z, x.z, u); u = fmaf(a.w, x.w, u);
        }
        u += __shfl_xor_sync(0xffffffffu, u, 1);
        if (c == 0) U[j * 16 + t] = u;
    }
    __syncthreads();

    // ---- P6: Wf[j] = F_j * sum_t AG[j][t]*U[j][t] ----
    if (tid < NJ) {
        const float4* u4 = (const float4*)(U  + tid * 16);
        const float4* a4 = (const float4*)(AG + tid * 16);
        float s = 0.f;
#pragma unroll
        for (int q = 0; q < 4; q++) {
            float4 u = u4[q], a = a4[q];
            s = fmaf(u.x, a.x, s); s = fmaf(u.y, a.y, s);
            s = fmaf(u.z, a.z, s); s = fmaf(u.w, a.w, s);
        }
        Wf[tid] = c_F[tid] * s;
    }
    __syncthreads();

    // ---- P7: y = q + sum_j Wf[j] q^j -> g_y ----
    if (tid < 128) {
        float val = Wf[NJ - 1];
#pragma unroll
        for (int j = NJ - 2; j >= 0; j--) val = fmaf(val, qv, Wf[j]);
        g_y[b * MM + h * 128 + tid] = qv + val;
    }
    __syncthreads();

    // ---- arrival counter; only the last block of each batch does LN ----
    if (tid == 0) {
        __threadfence();
        int old = atomicAdd(&g_cnt[b], 1);
        isLast = (old == HH - 1);
    }
    __syncthreads();
    if (!isLast) return;
    __threadfence();   // acquire

    // ---- LN tail: 512 threads, 4 y's each (L1-bypass loads) ----
    float4 y4 = __ldcg(((const float4*)(g_y + b * MM)) + tid);
    float s1 = (y4.x + y4.y) + (y4.z + y4.w);
    float s2 = fmaf(y4.x, y4.x, fmaf(y4.y, y4.y, fmaf(y4.z, y4.z, y4.w * y4.w)));
#pragma unroll
    for (int o = 16; o; o >>= 1) {
        s1 += __shfl_down_sync(0xffffffffu, s1, o);
        s2 += __shfl_down_sync(0xffffffffu, s2, o);
    }
    if (lane == 0) { redS[warp] = s1; redS2[warp] = s2; }
    __syncthreads();
    if (warp == 0) {
        float a = (lane < 16) ? redS[lane]  : 0.f;
        float c = (lane < 16) ? redS2[lane] : 0.f;
#pragma unroll
        for (int o = 8; o; o >>= 1) {
            a += __shfl_xor_sync(0xffffffffu, a, o);
            c += __shfl_xor_sync(0xffffffffu, c, o);
        }
        if (lane == 0) {
            float mu  = a * (1.0f / MM);
            float var = c * (1.0f / MM) - mu * mu;
            mu_s = mu;
            rs_s = rsqrtf(var + 1e-5f);
        }
    }
    __syncthreads();
    const float mu = mu_s, rs = rs_s;
    float4 o4;
    o4.x = (y4.x - mu) * rs * lw4.x + lb4.x;
    o4.y = (y4.y - mu) * rs * lw4.y + lb4.y;
    o4.z = (y4.z - mu) * rs * lw4.z + lb4.z;
    o4.w = (y4.w - mu) * rs * lw4.w + lb4.w;
    ((float4*)(out + b * MM))[tid] = o4;
    if (tid == 0) g_cnt[b] = 0;   // reset for next graph replay
}

extern "C" void kernel_launch(void* const* d_in, const int* in_sizes, int n_in,
                              void* d_out, int out_size) {
    const float* query = (const float*)d_in[0];
    const float* key_  = (const float*)d_in[1];
    const float* value = (const float*)d_in[2];
    const float* wq    = (const float*)d_in[3];
    const float* wk    = (const float*)d_in[4];
    const float* wv    = (const float*)d_in[5];
    const float* wf    = (const float*)d_in[6];
    const float* lw    = (const float*)d_in[7];
    const float* lb    = (const float*)d_in[8];
    float* out = (float*)d_out;

    k_fused<<<BB * HH, 512>>>(query, key_, value, wq, wk, wv, wf, lw, lb, out);
}